// round 1
// baseline (speedup 1.0000x reference)
#include <cuda_runtime.h>
#include <cuda_bf16.h>
#include <math.h>

#define LL   5
#define BB   256
#define HH   512
#define GG   2048
#define SS   128
#define VV   32000
#define KTOT 1024

#define NCTA 128
#define NTHR 256
#define BM   32
#define KT   32
#define NKT  (KTOT / KT)   // 32
#define NKTO (HH / KT)     // 16

// Persistent state (device globals: allocation-free scratch).
// h is double-buffered by step parity; c is updated in place (each (b,u) owned
// by exactly one thread of one CTA, so no cross-CTA hazard).
__device__ float g_h[2][LL][BB][HH];
__device__ float g_c[LL][BB][HH];
__device__ unsigned g_bar_count;  // zero-initialized
__device__ unsigned g_bar_gen;

__device__ __forceinline__ float sigf(float v) { return 1.0f / (1.0f + expf(-v)); }

// Software grid barrier. Safe: grid = 128 CTAs <= 148 SMs, __launch_bounds__
// guarantees 1-CTA residency, so all CTAs are co-resident in wave 1.
// Generation-based, deterministic, replay-safe (gen monotonically increases
// across graph replays; count always returns to 0).
__device__ __forceinline__ void grid_sync() {
    __syncthreads();
    if (threadIdx.x == 0) {
        __threadfence();
        unsigned gen = *((volatile unsigned*)&g_bar_gen);
        if (atomicAdd(&g_bar_count, 1u) == NCTA - 1u) {
            atomicExch(&g_bar_count, 0u);
            __threadfence();
            atomicAdd(&g_bar_gen, 1u);
        } else {
            while (*((volatile unsigned*)&g_bar_gen) == gen) { __nanosleep(32); }
        }
        __threadfence();
    }
    __syncthreads();
}

// CTA tiling: 128 CTAs = 8 batch-tiles (32 rows) x 16 unit-tiles (32 hidden units).
// Each CTA computes a 32x128 tile of gates where the 128 columns are
// gate-INTERLEAVED: local n = u*4 + gate, so each thread's 4 consecutive
// columns are (i,f,g,o) of ONE unit -> activation is done fully in registers.
__global__ void __launch_bounds__(NTHR, 1)
lstm_persistent(const int* __restrict__ x,
                const float* __restrict__ h0,
                const float* __restrict__ c0,
                const float* __restrict__ emb,
                const float* __restrict__ Wih_g,
                const float* __restrict__ Whh_g,
                const float* __restrict__ bih_g,
                const float* __restrict__ bhh_g,
                const float* __restrict__ Wout,
                const float* __restrict__ bout,
                float* __restrict__ out)
{
    __shared__ __align__(16) float A_s[KT][36];   // A^T: [k][batch], pad 36 keeps float4 16B-aligned (144B rows)
    __shared__ __align__(16) float W_s[KT][132];  // W^T: [k][gatecol], pad 132 (528B rows)
    __shared__ int tok_s[BM];

    const int tid = threadIdx.x;
    const int bid = blockIdx.x;
    const int mb  = bid >> 4;        // batch tile 0..7
    const int nb  = bid & 15;        // unit tile 0..15
    const int ty  = tid >> 5;        // 0..7  -> 4 batch rows each
    const int tx  = tid & 31;        // 0..31 -> one unit (4 gate cols)
    const int lb  = tid >> 3;        // 0..31 load row
    const int kc  = (tid & 7) << 2;  // 0..28 load k offset

    // ---- init: h0 -> parity-1 buffer (prev of step 0), c0 -> c ----
    for (int i = bid * NTHR + tid; i < LL * BB * HH; i += NCTA * NTHR) {
        ((float*)g_h)[LL * BB * HH + i] = h0[i];
        ((float*)g_c)[i] = c0[i];
    }
    grid_sync();

    for (int t = 0; t < SS; ++t) {
        const int cur  = t & 1;
        const int prev = cur ^ 1;
        // torch .view(S,B,-1) reinterpretation: token(t,b) = x_flat[t*B + b]
        if (tid < BM) tok_s[tid] = x[t * BB + mb * BM + tid];
        __syncthreads();

        #pragma unroll 1
        for (int l = 0; l < LL; ++l) {
            const float* __restrict__ hpv = &g_h[prev][l][0][0];
            const float* __restrict__ hin = &g_h[cur][(l == 0 ? 0 : l - 1)][0][0];
            const float* __restrict__ Wih = Wih_g + l * GG * HH;
            const float* __restrict__ Whh = Whh_g + l * GG * HH;
            const bool use_emb = (l == 0);

            float acc[4][4];
            #pragma unroll
            for (int i = 0; i < 4; ++i)
                #pragma unroll
                for (int j = 0; j < 4; ++j) acc[i][j] = 0.0f;

            float4 av, wv[4];
            // prologue: load k-tile 0 (k = kc < 512, always the "input" half)
            {
                const float* ar = use_emb ? (emb + (size_t)tok_s[lb] * HH + kc)
                                          : (hin + (size_t)(mb * BM + lb) * HH + kc);
                av = *(const float4*)ar;
                #pragma unroll
                for (int j = 0; j < 4; ++j) {
                    const int n = lb + 32 * j;                       // gate-interleaved col
                    const int grow = (n & 3) * HH + nb * 32 + (n >> 2);
                    wv[j] = *(const float4*)(Wih + (size_t)grow * HH + kc);
                }
            }

            #pragma unroll 1
            for (int kt = 0; kt < NKT; ++kt) {
                __syncthreads();   // previous compute done reading smem
                A_s[kc + 0][lb] = av.x; A_s[kc + 1][lb] = av.y;
                A_s[kc + 2][lb] = av.z; A_s[kc + 3][lb] = av.w;
                #pragma unroll
                for (int j = 0; j < 4; ++j) {
                    const int n = lb + 32 * j;
                    W_s[kc + 0][n] = wv[j].x; W_s[kc + 1][n] = wv[j].y;
                    W_s[kc + 2][n] = wv[j].z; W_s[kc + 3][n] = wv[j].w;
                }
                __syncthreads();
                if (kt + 1 < NKT) {   // software pipeline: next tile loads overlap compute
                    const int k = (kt + 1) * KT + kc;
                    const float* ar;
                    if (k < HH) ar = use_emb ? (emb + (size_t)tok_s[lb] * HH + k)
                                             : (hin + (size_t)(mb * BM + lb) * HH + k);
                    else        ar = hpv + (size_t)(mb * BM + lb) * HH + (k - HH);
                    av = *(const float4*)ar;
                    #pragma unroll
                    for (int j = 0; j < 4; ++j) {
                        const int n = lb + 32 * j;
                        const int grow = (n & 3) * HH + nb * 32 + (n >> 2);
                        wv[j] = (k < HH) ? *(const float4*)(Wih + (size_t)grow * HH + k)
                                         : *(const float4*)(Whh + (size_t)grow * HH + (k - HH));
                    }
                }
                #pragma unroll
                for (int kk = 0; kk < KT; ++kk) {
                    const float4 a = *(const float4*)(&A_s[kk][ty << 2]);  // warp-broadcast
                    const float4 w = *(const float4*)(&W_s[kk][tx << 2]);  // conflict-free
                    acc[0][0] += a.x * w.x; acc[0][1] += a.x * w.y; acc[0][2] += a.x * w.z; acc[0][3] += a.x * w.w;
                    acc[1][0] += a.y * w.x; acc[1][1] += a.y * w.y; acc[1][2] += a.y * w.z; acc[1][3] += a.y * w.w;
                    acc[2][0] += a.z * w.x; acc[2][1] += a.z * w.y; acc[2][2] += a.z * w.z; acc[2][3] += a.z * w.w;
                    acc[3][0] += a.w * w.x; acc[3][1] += a.w * w.y; acc[3][2] += a.w * w.z; acc[3][3] += a.w * w.w;
                }
            }

            // ---- activation: thread owns unit u for 4 batches, all 4 gates ----
            const int u = nb * 32 + tx;
            const float bi = bih_g[l * GG + u]           + bhh_g[l * GG + u];
            const float bf = bih_g[l * GG + HH + u]      + bhh_g[l * GG + HH + u];
            const float bg = bih_g[l * GG + 2 * HH + u]  + bhh_g[l * GG + 2 * HH + u];
            const float bo = bih_g[l * GG + 3 * HH + u]  + bhh_g[l * GG + 3 * HH + u];
            #pragma unroll
            for (int i = 0; i < 4; ++i) {
                const int b = mb * BM + (ty << 2) + i;
                const float ig = sigf(acc[i][0] + bi);
                const float fg = sigf(acc[i][1] + bf);
                const float gg = tanhf(acc[i][2] + bg);
                const float og = sigf(acc[i][3] + bo);
                const float cn = fg * g_c[l][b][u] + ig * gg;
                g_c[l][b][u] = cn;
                g_h[cur][l][b][u] = og * tanhf(cn);
            }
            grid_sync();   // h[cur][l] complete before layer l+1 reads it
        }
    }

    // ---- output GEMM: logits(256 x 32000) = h_final @ Wout^T + bout ----
    // 2000 independent 32x128 tiles, persistent-looped over 128 CTAs.
    const float* __restrict__ hfin = &g_h[(SS - 1) & 1][LL - 1][0][0];
    #pragma unroll 1
    for (int tile = bid; tile < 8 * 250; tile += NCTA) {
        const int b0 = (tile / 250) * 32;
        const int v0 = (tile % 250) * 128;
        float acc[4][4];
        #pragma unroll
        for (int i = 0; i < 4; ++i)
            #pragma unroll
            for (int j = 0; j < 4; ++j) acc[i][j] = 0.0f;

        float4 av, wv[4];
        av = *(const float4*)(hfin + (size_t)(b0 + lb) * HH + kc);
        #pragma unroll
        for (int j = 0; j < 4; ++j)
            wv[j] = *(const float4*)(Wout + (size_t)(v0 + lb + 32 * j) * HH + kc);

        #pragma unroll 1
        for (int kt = 0; kt < NKTO; ++kt) {
            __syncthreads();
            A_s[kc + 0][lb] = av.x; A_s[kc + 1][lb] = av.y;
            A_s[kc + 2][lb] = av.z; A_s[kc + 3][lb] = av.w;
            #pragma unroll
            for (int j = 0; j < 4; ++j) {
                const int n = lb + 32 * j;    // plain mapping: col n -> v0+n
                W_s[kc + 0][n] = wv[j].x; W_s[kc + 1][n] = wv[j].y;
                W_s[kc + 2][n] = wv[j].z; W_s[kc + 3][n] = wv[j].w;
            }
            __syncthreads();
            if (kt + 1 < NKTO) {
                const int k = (kt + 1) * KT + kc;
                av = *(const float4*)(hfin + (size_t)(b0 + lb) * HH + k);
                #pragma unroll
                for (int j = 0; j < 4; ++j)
                    wv[j] = *(const float4*)(Wout + (size_t)(v0 + lb + 32 * j) * HH + k);
            }
            #pragma unroll
            for (int kk = 0; kk < KT; ++kk) {
                const float4 a = *(const float4*)(&A_s[kk][ty << 2]);
                const float4 w = *(const float4*)(&W_s[kk][tx << 2]);
                acc[0][0] += a.x * w.x; acc[0][1] += a.x * w.y; acc[0][2] += a.x * w.z; acc[0][3] += a.x * w.w;
                acc[1][0] += a.y * w.x; acc[1][1] += a.y * w.y; acc[1][2] += a.y * w.z; acc[1][3] += a.y * w.w;
                acc[2][0] += a.z * w.x; acc[2][1] += a.z * w.y; acc[2][2] += a.z * w.z; acc[2][3] += a.z * w.w;
                acc[3][0] += a.w * w.x; acc[3][1] += a.w * w.y; acc[3][2] += a.w * w.z; acc[3][3] += a.w * w.w;
            }
        }
        #pragma unroll
        for (int i = 0; i < 4; ++i) {
            const int b = b0 + (ty << 2) + i;
            const int v = v0 + (tx << 2);
            float4 r;
            r.x = acc[i][0] + bout[v + 0];
            r.y = acc[i][1] + bout[v + 1];
            r.z = acc[i][2] + bout[v + 2];
            r.w = acc[i][3] + bout[v + 3];
            *(float4*)(out + (size_t)b * VV + v) = r;
        }
    }
}

extern "C" void kernel_launch(void* const* d_in, const int* in_sizes, int n_in,
                              void* d_out, int out_size) {
    (void)in_sizes; (void)n_in; (void)out_size;
    lstm_persistent<<<NCTA, NTHR>>>(
        (const int*)  d_in[0],   // x        (B,S) int32
        (const float*)d_in[1],   // h0       (L,B,H)
        (const float*)d_in[2],   // c0       (L,B,H)
        (const float*)d_in[3],   // emb      (V,H)
        (const float*)d_in[4],   // W_ih     (L,4H,H)
        (const float*)d_in[5],   // W_hh     (L,4H,H)
        (const float*)d_in[6],   // b_ih     (L,4H)
        (const float*)d_in[7],   // b_hh     (L,4H)
        (const float*)d_in[8],   // W_out    (V,H)
        (const float*)d_in[9],   // b_out    (V,)
        (float*)d_out);          // (B,V) float32
}